// round 10
// baseline (speedup 1.0000x reference)
#include <cuda_runtime.h>
#include <math.h>
#include <stdint.h>

#define T_LEN 131072
#define NS 64
#define MD 8
#define NCH 1480          // chunks: 2 per CTA, 740 CTAs (5 CTAs/SM, one wave)
#define L_BASE 88         // 131071 = 1480*88 + 831
#define L_REM 831         // first 831 chunks have length 89
#define BURN 32           // burn-in steps (Perron direction warm-up)

// ---- static device scratch ----
__device__ float g_w[(size_t)T_LEN * NS];     // w[t][s] = exp(em - max)
__device__ float g_maxlog[T_LEN];
__device__ float g_loglam[NS * MD];
__device__ float g_lamsum[NS];
__device__ float g_Alin[NS * NS];
__device__ double g_S1[NCH];
__device__ double g_lgam[32];
__device__ unsigned int g_hist[32];

__device__ __forceinline__ int chunk_t0(int c) { return 1 + c * L_BASE + (c < L_REM ? c : L_REM); }
__device__ __forceinline__ int chunk_len(int c) { return L_BASE + (c < L_REM ? 1 : 0); }

#define BAR64(id) asm volatile("bar.sync %0, 64;" :: "r"(id) : "memory")

// ============================================================
__global__ void setup_kernel(const float* __restrict__ lambdas,
                             const float* __restrict__ log_transition) {
    int tid = threadIdx.x;
    for (int idx = tid; idx < NS * MD; idx += blockDim.x)
        g_loglam[idx] = logf(lambdas[idx]);
    if (tid < NS) {
        float s = 0.f;
        #pragma unroll
        for (int m = 0; m < MD; m++) s += lambdas[tid * MD + m];
        g_lamsum[tid] = s;
    }
    for (int idx = tid; idx < NS * NS; idx += blockDim.x)
        g_Alin[idx] = expf(log_transition[idx]);
    if (tid < 32) {
        g_hist[tid] = 0u;
        g_lgam[tid] = lgamma((double)tid + 1.0);   // precomputed, off hot path
    }
}

// ============================================================
// Pass 0: emission weights + maxlog + x-histogram.
// ============================================================
__global__ void __launch_bounds__(256) pass0_kernel(const int* __restrict__ x) {
    __shared__ float sll[NS * MD];
    __shared__ float slam[NS];
    __shared__ unsigned int shist[32];
    int tid = threadIdx.x;
    for (int idx = tid; idx < NS * MD; idx += blockDim.x) sll[idx] = g_loglam[idx];
    if (tid < NS) slam[tid] = g_lamsum[tid];
    if (tid < 32) shist[tid] = 0u;
    __syncthreads();

    int warp = tid >> 5, lane = tid & 31;
    int t = blockIdx.x * 8 + warp;

    int4 xa = *(const int4*)&x[(size_t)t * MD];
    int4 xb = *(const int4*)&x[(size_t)t * MD + 4];
    int xv[8] = {xa.x, xa.y, xa.z, xa.w, xb.x, xb.y, xb.z, xb.w};
    if (lane < 8) atomicAdd(&shist[xv[lane] & 31], 1u);

    float e0 = -slam[lane], e1 = -slam[lane + 32];
    #pragma unroll
    for (int m = 0; m < 8; m++) {
        float xm = (float)xv[m];
        e0 = fmaf(xm, sll[lane * MD + m], e0);
        e1 = fmaf(xm, sll[(lane + 32) * MD + m], e1);
    }
    float mx = fmaxf(e0, e1);
    #pragma unroll
    for (int o = 16; o > 0; o >>= 1)
        mx = fmaxf(mx, __shfl_xor_sync(0xffffffffu, mx, o));
    g_w[(size_t)t * NS + lane]      = expf(e0 - mx);
    g_w[(size_t)t * NS + lane + 32] = expf(e1 - mx);
    if (lane == 0) g_maxlog[t] = mx;

    __syncthreads();
    if (tid < 32 && shist[tid]) atomicAdd(&g_hist[tid], shist[tid]);
}

// ============================================================
// Pass 1 (vector scan, lag-2 deferred normalization):
// 2 chunks per CTA, 64 threads each, thread i holds A row i in regs.
//   v_t = (1/s_{t-2}) * w_t  .* (A v_{t-1})
// s_{t-1} (1-norm of prev round's output) is reduced INSIDE round t,
// fully overlapped with the matvec; its value is consumed at round t+1.
// Exact accounting (telescoped):
//   c>0 : S = log s_{t0-2} + sum_{tau=t0..tend-3} log s_tau
//             + log s_{tend-1} + sum maxlog[t0..tend-1]
//   c==0: S = initmax + sum_{tau=tb-1..tend-3} log s_tau
//             + log s_{tend-1} + sum maxlog
// ============================================================
__global__ void __launch_bounds__(128, 5) pass1_vec(const int* __restrict__ x,
                                                    const float* __restrict__ priors) {
    __shared__ float sal[2][2][NS];     // [chunk][parity][state]
    __shared__ float ssum[2][2][2];     // [chunk][slot=t&1][warp-half]
    __shared__ float sinit[2];          // chunk-0 init max halves

    int tid = threadIdx.x;
    int ch = tid >> 6;                  // chunk slot in CTA
    int i = tid & 63;                   // state index
    int h = (tid >> 5) & 1;             // warp-half within chunk
    int lane = tid & 31;
    int c = blockIdx.x * 2 + ch;
    int t0 = chunk_t0(c);
    int L = chunk_len(c);
    int tb = (c == 0) ? 1 : t0 - BURN;
    int tend = t0 + L;
    int barid = ch + 1;

    // A row i -> 64 registers
    float arow[NS];
    {
        const float4* ap = (const float4*)&g_Alin[i * NS];
        #pragma unroll
        for (int q = 0; q < 16; q++) {
            float4 v = ap[q];
            arow[4 * q]     = v.x; arow[4 * q + 1] = v.y;
            arow[4 * q + 2] = v.z; arow[4 * q + 3] = v.w;
        }
    }

    float prev_val;     // my component of v_{t-1} (unreduced)
    double S = 0.0;
    if (c == 0) {
        float e = priors[i] - g_lamsum[i];
        #pragma unroll
        for (int m = 0; m < MD; m++)
            e = fmaf((float)x[m], g_loglam[i * MD + m], e);
        float mx = e;
        #pragma unroll
        for (int o = 16; o > 0; o >>= 1)
            mx = fmaxf(mx, __shfl_xor_sync(0xffffffffu, mx, o));
        if (lane == 0) sinit[h] = mx;
        __syncthreads();
        mx = fmaxf(sinit[0], sinit[1]);
        prev_val = expf(e - mx);
        S = (double)mx;
    } else {
        prev_val = 1.0f;   // uniform start; burn-in washes direction
        __syncthreads();
    }
    sal[ch][0][i] = prev_val;
    __syncthreads();

    int p = 0;
    for (int t = tb; t < tend; t++) {
        BAR64(barid);   // sal[p] + ssum[(t-1)&1] (written in round t-1) visible

        float w = __ldg(&g_w[(size_t)t * NS + i]);

        // lag-2 scale: s_{t-2}, reduced during round t-1 (slot (t-1)&1)
        float s_lag = 1.0f, inv = 1.0f;
        if (t > tb) {
            s_lag = ssum[ch][(t - 1) & 1][0] + ssum[ch][(t - 1) & 1][1];
            inv = __frcp_rn(s_lag);
        }

        // matvec (broadcast reads, conflict-free)
        const float4* av = (const float4*)sal[ch][p];
        float a0 = 0.f, a1 = 0.f, a2 = 0.f, a3 = 0.f;
        #pragma unroll
        for (int q = 0; q < 16; q++) {
            float4 v = av[q];
            a0 = fmaf(arow[4 * q],     v.x, a0);
            a1 = fmaf(arow[4 * q + 1], v.y, a1);
            a2 = fmaf(arow[4 * q + 2], v.z, a2);
            a3 = fmaf(arow[4 * q + 3], v.w, a3);
        }
        float val = ((a0 + a1) + (a2 + a3)) * (w * inv);
        sal[ch][p ^ 1][i] = val;

        // pipelined reduce of PREVIOUS round's output -> s_{t-1} (slot t&1)
        float r = prev_val;
        #pragma unroll
        for (int o = 16; o > 0; o >>= 1)
            r += __shfl_xor_sync(0xffffffffu, r, o);
        if (lane == 0) ssum[ch][t & 1][h] = r;

        if (i == 0) {
            if (t > tb) {
                int tau = t - 2;
                bool acc = (c == 0) || (tau == t0 - 2) || (tau >= t0 && tau <= tend - 3);
                if (acc) S += (double)__logf(s_lag);
            }
            if (t >= t0) S += (double)__ldg(&g_maxlog[t]);
        }
        prev_val = val;
        p ^= 1;
    }

    // final norm s_{tend-1}
    BAR64(barid);
    {
        float r = prev_val;
        #pragma unroll
        for (int o = 16; o > 0; o >>= 1)
            r += __shfl_xor_sync(0xffffffffu, r, o);
        if (lane == 0) ssum[ch][tend & 1][h] = r;
    }
    BAR64(barid);
    if (i == 0) {
        float s_end = ssum[ch][tend & 1][0] + ssum[ch][tend & 1][1];
        g_S1[c] = S + (double)__logf(s_end);
    }
}

// ============================================================
// Final: out = sum_c S_c - sum_b hist[b]*lgamma(b+1)
// ============================================================
__global__ void __launch_bounds__(256) final_kernel(float* __restrict__ out) {
    __shared__ double sp[8];
    int tid = threadIdx.x, lane = tid & 31, wid = tid >> 5;
    double s = 0.0;
    for (int c = tid; c < NCH; c += 256) s += g_S1[c];
    #pragma unroll
    for (int o = 16; o > 0; o >>= 1)
        s += __shfl_xor_sync(0xffffffffu, s, o);
    if (lane == 0) sp[wid] = s;
    __syncthreads();
    if (tid == 0) {
        double tot = 0.0;
        #pragma unroll
        for (int q = 0; q < 8; q++) tot += sp[q];
        double lgam = 0.0;
        #pragma unroll
        for (int b = 0; b < 32; b++) {
            unsigned int cnt = g_hist[b];
            if (cnt) lgam += (double)cnt * g_lgam[b];
        }
        out[0] = (float)(tot - lgam);
    }
}

// ============================================================
extern "C" void kernel_launch(void* const* d_in, const int* in_sizes, int n_in,
                              void* d_out, int out_size) {
    const int*   x              = (const int*)d_in[0];
    const float* lambdas        = (const float*)d_in[1];
    const float* log_transition = (const float*)d_in[2];
    const float* priors         = (const float*)d_in[3];
    float* out = (float*)d_out;

    setup_kernel<<<1, 256>>>(lambdas, log_transition);
    pass0_kernel<<<T_LEN / 8, 256>>>(x);
    pass1_vec<<<NCH / 2, 128>>>(x, priors);
    final_kernel<<<1, 256>>>(out);
}

// round 11
// speedup vs baseline: 1.6802x; 1.6802x over previous
#include <cuda_runtime.h>
#include <math.h>
#include <stdint.h>

#define T_LEN 131072
#define NS 64
#define MD 8
#define NCH 1184          // chunks: 2 per CTA, 592 CTAs (4 CTAs/SM, one wave)
#define L_BASE 110        // 131071 = 1184*110 + 831
#define L_REM 831         // first 831 chunks have length 111
#define BURN 32           // burn-in steps (Perron direction warm-up)

// ---- static device scratch ----
__device__ float g_w[(size_t)T_LEN * NS];     // w[t][s] = exp(em - max)
__device__ float g_maxlog[T_LEN];
__device__ float g_loglam[NS * MD];
__device__ float g_lamsum[NS];
__device__ float g_Alin[NS * NS];
__device__ double g_S1[NCH];
__device__ double g_lgam[32];
__device__ unsigned int g_hist[32];

__device__ __forceinline__ int chunk_t0(int c) { return 1 + c * L_BASE + (c < L_REM ? c : L_REM); }
__device__ __forceinline__ int chunk_len(int c) { return L_BASE + (c < L_REM ? 1 : 0); }

#define BAR64(id) asm volatile("bar.sync %0, 64;" :: "r"(id) : "memory")

// ============================================================
__global__ void setup_kernel(const float* __restrict__ lambdas,
                             const float* __restrict__ log_transition) {
    int tid = threadIdx.x;
    for (int idx = tid; idx < NS * MD; idx += blockDim.x)
        g_loglam[idx] = logf(lambdas[idx]);
    if (tid < NS) {
        float s = 0.f;
        #pragma unroll
        for (int m = 0; m < MD; m++) s += lambdas[tid * MD + m];
        g_lamsum[tid] = s;
    }
    for (int idx = tid; idx < NS * NS; idx += blockDim.x)
        g_Alin[idx] = expf(log_transition[idx]);
    if (tid < 32) {
        g_hist[tid] = 0u;
        g_lgam[tid] = lgamma((double)tid + 1.0);   // precomputed, off hot path
    }
}

// ============================================================
// Pass 0: emission weights + maxlog + x-histogram.
// ============================================================
__global__ void __launch_bounds__(256) pass0_kernel(const int* __restrict__ x) {
    __shared__ float sll[NS * MD];
    __shared__ float slam[NS];
    __shared__ unsigned int shist[32];
    int tid = threadIdx.x;
    for (int idx = tid; idx < NS * MD; idx += blockDim.x) sll[idx] = g_loglam[idx];
    if (tid < NS) slam[tid] = g_lamsum[tid];
    if (tid < 32) shist[tid] = 0u;
    __syncthreads();

    int warp = tid >> 5, lane = tid & 31;
    int t = blockIdx.x * 8 + warp;

    int4 xa = *(const int4*)&x[(size_t)t * MD];
    int4 xb = *(const int4*)&x[(size_t)t * MD + 4];
    int xv[8] = {xa.x, xa.y, xa.z, xa.w, xb.x, xb.y, xb.z, xb.w};
    if (lane < 8) atomicAdd(&shist[xv[lane] & 31], 1u);

    float e0 = -slam[lane], e1 = -slam[lane + 32];
    #pragma unroll
    for (int m = 0; m < 8; m++) {
        float xm = (float)xv[m];
        e0 = fmaf(xm, sll[lane * MD + m], e0);
        e1 = fmaf(xm, sll[(lane + 32) * MD + m], e1);
    }
    float mx = fmaxf(e0, e1);
    #pragma unroll
    for (int o = 16; o > 0; o >>= 1)
        mx = fmaxf(mx, __shfl_xor_sync(0xffffffffu, mx, o));
    g_w[(size_t)t * NS + lane]      = expf(e0 - mx);
    g_w[(size_t)t * NS + lane + 32] = expf(e1 - mx);
    if (lane == 0) g_maxlog[t] = mx;

    __syncthreads();
    if (tid < 32 && shist[tid]) atomicAdd(&g_hist[tid], shist[tid]);
}

// ============================================================
// Pass 1 (vector scan, lag-2 deferred normalization):
// 2 chunks per CTA, 64 threads each, thread i holds A row i in regs
// (4 CTAs/SM -> 128-reg cap, no spill of the 64-reg A row).
//   v_t = (1/s_{t-2}) * w_t .* (A v_{t-1})
// s_{t-1} is reduced INSIDE round t (off critical path), consumed at t+1.
// Telescoped accounting keeps the result exact.
// ============================================================
__global__ void __launch_bounds__(128, 4) pass1_vec(const int* __restrict__ x,
                                                    const float* __restrict__ priors) {
    __shared__ float sal[2][2][NS];     // [chunk][parity][state]
    __shared__ float ssum[2][2][2];     // [chunk][slot=t&1][warp-half]
    __shared__ float sinit[2];          // chunk-0 init max halves

    int tid = threadIdx.x;
    int ch = tid >> 6;                  // chunk slot in CTA
    int i = tid & 63;                   // state index
    int h = (tid >> 5) & 1;             // warp-half within chunk
    int lane = tid & 31;
    int c = blockIdx.x * 2 + ch;
    int t0 = chunk_t0(c);
    int L = chunk_len(c);
    int tb = (c == 0) ? 1 : t0 - BURN;
    int tend = t0 + L;
    int barid = ch + 1;

    // A row i -> 64 registers
    float arow[NS];
    {
        const float4* ap = (const float4*)&g_Alin[i * NS];
        #pragma unroll
        for (int q = 0; q < 16; q++) {
            float4 v = ap[q];
            arow[4 * q]     = v.x; arow[4 * q + 1] = v.y;
            arow[4 * q + 2] = v.z; arow[4 * q + 3] = v.w;
        }
    }

    float prev_val;     // my component of v_{t-1} (unreduced)
    double S = 0.0;
    if (c == 0) {
        float e = priors[i] - g_lamsum[i];
        #pragma unroll
        for (int m = 0; m < MD; m++)
            e = fmaf((float)x[m], g_loglam[i * MD + m], e);
        float mx = e;
        #pragma unroll
        for (int o = 16; o > 0; o >>= 1)
            mx = fmaxf(mx, __shfl_xor_sync(0xffffffffu, mx, o));
        if (lane == 0) sinit[h] = mx;
        __syncthreads();
        mx = fmaxf(sinit[0], sinit[1]);
        prev_val = expf(e - mx);
        S = (double)mx;
    } else {
        prev_val = 1.0f;   // uniform start; burn-in washes direction
        __syncthreads();
    }
    sal[ch][0][i] = prev_val;
    __syncthreads();

    int p = 0;
    for (int t = tb; t < tend; t++) {
        BAR64(barid);   // sal[p] + ssum[(t-1)&1] (written in round t-1) visible

        float w = __ldg(&g_w[(size_t)t * NS + i]);

        // lag-2 scale: s_{t-2}, reduced during round t-1 (slot (t-1)&1)
        float s_lag = 1.0f, inv = 1.0f;
        if (t > tb) {
            s_lag = ssum[ch][(t - 1) & 1][0] + ssum[ch][(t - 1) & 1][1];
            inv = __frcp_rn(s_lag);
        }

        // matvec (broadcast reads, conflict-free)
        const float4* av = (const float4*)sal[ch][p];
        float a0 = 0.f, a1 = 0.f, a2 = 0.f, a3 = 0.f;
        #pragma unroll
        for (int q = 0; q < 16; q++) {
            float4 v = av[q];
            a0 = fmaf(arow[4 * q],     v.x, a0);
            a1 = fmaf(arow[4 * q + 1], v.y, a1);
            a2 = fmaf(arow[4 * q + 2], v.z, a2);
            a3 = fmaf(arow[4 * q + 3], v.w, a3);
        }
        float val = ((a0 + a1) + (a2 + a3)) * (w * inv);
        sal[ch][p ^ 1][i] = val;

        // pipelined reduce of PREVIOUS round's output -> s_{t-1} (slot t&1)
        float r = prev_val;
        #pragma unroll
        for (int o = 16; o > 0; o >>= 1)
            r += __shfl_xor_sync(0xffffffffu, r, o);
        if (lane == 0) ssum[ch][t & 1][h] = r;

        if (i == 0) {
            if (t > tb) {
                int tau = t - 2;
                bool acc = (c == 0) || (tau == t0 - 2) || (tau >= t0 && tau <= tend - 3);
                if (acc) S += (double)__logf(s_lag);
            }
            if (t >= t0) S += (double)__ldg(&g_maxlog[t]);
        }
        prev_val = val;
        p ^= 1;
    }

    // final norm s_{tend-1}
    BAR64(barid);
    {
        float r = prev_val;
        #pragma unroll
        for (int o = 16; o > 0; o >>= 1)
            r += __shfl_xor_sync(0xffffffffu, r, o);
        if (lane == 0) ssum[ch][tend & 1][h] = r;
    }
    BAR64(barid);
    if (i == 0) {
        float s_end = ssum[ch][tend & 1][0] + ssum[ch][tend & 1][1];
        g_S1[c] = S + (double)__logf(s_end);
    }
}

// ============================================================
// Final: out = sum_c S_c - sum_b hist[b]*lgamma(b+1)
// ============================================================
__global__ void __launch_bounds__(256) final_kernel(float* __restrict__ out) {
    __shared__ double sp[8];
    int tid = threadIdx.x, lane = tid & 31, wid = tid >> 5;
    double s = 0.0;
    for (int c = tid; c < NCH; c += 256) s += g_S1[c];
    #pragma unroll
    for (int o = 16; o > 0; o >>= 1)
        s += __shfl_xor_sync(0xffffffffu, s, o);
    if (lane == 0) sp[wid] = s;
    __syncthreads();
    if (tid == 0) {
        double tot = 0.0;
        #pragma unroll
        for (int q = 0; q < 8; q++) tot += sp[q];
        double lgam = 0.0;
        #pragma unroll
        for (int b = 0; b < 32; b++) {
            unsigned int cnt = g_hist[b];
            if (cnt) lgam += (double)cnt * g_lgam[b];
        }
        out[0] = (float)(tot - lgam);
    }
}

// ============================================================
extern "C" void kernel_launch(void* const* d_in, const int* in_sizes, int n_in,
                              void* d_out, int out_size) {
    const int*   x              = (const int*)d_in[0];
    const float* lambdas        = (const float*)d_in[1];
    const float* log_transition = (const float*)d_in[2];
    const float* priors         = (const float*)d_in[3];
    float* out = (float*)d_out;

    setup_kernel<<<1, 256>>>(lambdas, log_transition);
    pass0_kernel<<<T_LEN / 8, 256>>>(x);
    pass1_vec<<<NCH / 2, 128>>>(x, priors);
    final_kernel<<<1, 256>>>(out);
}

// round 12
// speedup vs baseline: 1.7950x; 1.0683x over previous
#include <cuda_runtime.h>
#include <math.h>
#include <stdint.h>

#define T_LEN 131072
#define NS 64
#define MD 8
#define NCH 1184          // chunks: 2 per CTA, 592 CTAs (4 CTAs/SM, one wave)
#define GRID1 (NCH / 2)
#define L_BASE 110        // 131071 = 1184*110 + 831
#define L_REM 831         // first 831 chunks have length 111
#define BURN 32           // burn-in steps (Perron direction warm-up)

// ---- static device scratch ----
__device__ float g_w[(size_t)T_LEN * NS];     // w[t][s] = exp(em - max)
__device__ float g_maxlog[T_LEN];             // max_i em[t,i]  -  sum_m lgamma(x[t,m]+1)
__device__ float g_loglam[NS * MD];
__device__ float g_lamsum[NS];
__device__ float g_Alin[NS * NS];
__device__ float g_S1[NCH];
__device__ float g_lgamf[32];                 // lgamma(n+1), float
__device__ unsigned int g_cnt = 0;            // last-block counter (reset by last block)

__device__ __forceinline__ int chunk_t0(int c) { return 1 + c * L_BASE + (c < L_REM ? c : L_REM); }
__device__ __forceinline__ int chunk_len(int c) { return L_BASE + (c < L_REM ? 1 : 0); }

#define BAR64(id) asm volatile("bar.sync %0, 64;" :: "r"(id) : "memory")

// ============================================================
__global__ void setup_kernel(const float* __restrict__ lambdas,
                             const float* __restrict__ log_transition) {
    int tid = threadIdx.x;
    for (int idx = tid; idx < NS * MD; idx += blockDim.x)
        g_loglam[idx] = logf(lambdas[idx]);
    if (tid < NS) {
        float s = 0.f;
        #pragma unroll
        for (int m = 0; m < MD; m++) s += lambdas[tid * MD + m];
        g_lamsum[tid] = s;
    }
    for (int idx = tid; idx < NS * NS; idx += blockDim.x)
        g_Alin[idx] = expf(log_transition[idx]);
    if (tid < 32) g_lgamf[tid] = (float)lgamma((double)tid + 1.0);
}

// ============================================================
// Pass 0: w[t][s] + combined maxlog (emission max minus lgamma sum).
// ============================================================
__global__ void __launch_bounds__(256) pass0_kernel(const int* __restrict__ x) {
    __shared__ float sll[NS * MD];
    __shared__ float slam[NS];
    __shared__ float slg[32];
    int tid = threadIdx.x;
    for (int idx = tid; idx < NS * MD; idx += blockDim.x) sll[idx] = g_loglam[idx];
    if (tid < NS) slam[tid] = g_lamsum[tid];
    if (tid < 32) slg[tid] = g_lgamf[tid];
    __syncthreads();

    int warp = tid >> 5, lane = tid & 31;
    int t = blockIdx.x * 8 + warp;

    int4 xa = *(const int4*)&x[(size_t)t * MD];
    int4 xb = *(const int4*)&x[(size_t)t * MD + 4];
    int xv[8] = {xa.x, xa.y, xa.z, xa.w, xb.x, xb.y, xb.z, xb.w};

    float e0 = -slam[lane], e1 = -slam[lane + 32];
    #pragma unroll
    for (int m = 0; m < 8; m++) {
        float xm = (float)xv[m];
        e0 = fmaf(xm, sll[lane * MD + m], e0);
        e1 = fmaf(xm, sll[(lane + 32) * MD + m], e1);
    }
    float mx = fmaxf(e0, e1);
    #pragma unroll
    for (int o = 16; o > 0; o >>= 1)
        mx = fmaxf(mx, __shfl_xor_sync(0xffffffffu, mx, o));
    g_w[(size_t)t * NS + lane]      = expf(e0 - mx);
    g_w[(size_t)t * NS + lane + 32] = expf(e1 - mx);
    if (lane == 0) {
        float lg = 0.f;
        #pragma unroll
        for (int m = 0; m < 8; m++) lg += slg[xv[m] & 31];
        g_maxlog[t] = mx - lg;   // lgamma folded in
    }
}

// ============================================================
// Pass 1 (vector scan, lag-2 normalization, prefetched weights):
// 2 chunks per CTA, 64 threads each; thread i holds A row i in regs.
// w[t+1]/maxlog[t+1] prefetched one full round ahead (hides L2/DRAM).
// S accumulated in float (no FP64 chain). Last CTA reduces g_S1 -> out.
// ============================================================
__global__ void __launch_bounds__(128, 4) pass1_vec(const int* __restrict__ x,
                                                    const float* __restrict__ priors,
                                                    float* __restrict__ out) {
    __shared__ float sal[2][2][NS];     // [chunk][parity][state]
    __shared__ float ssum[2][2][2];     // [chunk][slot=t&1][warp-half]
    __shared__ float sinit[2];
    __shared__ int slast;
    __shared__ double sred[4];

    int tid = threadIdx.x;
    int ch = tid >> 6;
    int i = tid & 63;
    int h = (tid >> 5) & 1;
    int lane = tid & 31;
    int c = blockIdx.x * 2 + ch;
    int t0 = chunk_t0(c);
    int L = chunk_len(c);
    int tb = (c == 0) ? 1 : t0 - BURN;
    int tend = t0 + L;
    int barid = ch + 1;

    // A row i -> 64 registers
    float arow[NS];
    {
        const float4* ap = (const float4*)&g_Alin[i * NS];
        #pragma unroll
        for (int q = 0; q < 16; q++) {
            float4 v = ap[q];
            arow[4 * q]     = v.x; arow[4 * q + 1] = v.y;
            arow[4 * q + 2] = v.z; arow[4 * q + 3] = v.w;
        }
    }

    float prev_val;
    float S = 0.f;
    if (c == 0) {
        float e = priors[i] - g_lamsum[i];
        #pragma unroll
        for (int m = 0; m < MD; m++)
            e = fmaf((float)x[m], g_loglam[i * MD + m], e);
        float mx = e;
        #pragma unroll
        for (int o = 16; o > 0; o >>= 1)
            mx = fmaxf(mx, __shfl_xor_sync(0xffffffffu, mx, o));
        if (lane == 0) sinit[h] = mx;
        __syncthreads();
        mx = fmaxf(sinit[0], sinit[1]);
        prev_val = expf(e - mx);
        if (i == 0) {
            float lg0 = 0.f;   // t=0's lgamma term (not covered by maxlog loop)
            #pragma unroll
            for (int m = 0; m < 8; m++) lg0 += g_lgamf[x[m] & 31];
            S = mx - lg0;
        }
    } else {
        prev_val = 1.0f;
        __syncthreads();
    }
    sal[ch][0][i] = prev_val;
    __syncthreads();

    // preload step tb
    float w = __ldg(&g_w[(size_t)tb * NS + i]);
    float ml = (i == 0) ? __ldg(&g_maxlog[tb]) : 0.f;

    int p = 0;
    for (int t = tb; t < tend; t++) {
        // prefetch NEXT step's weight + maxlog (lands during this round)
        float wn = 0.f, mln = 0.f;
        if (t + 1 < tend) {
            wn = __ldg(&g_w[(size_t)(t + 1) * NS + i]);
            if (i == 0) mln = __ldg(&g_maxlog[t + 1]);
        }

        BAR64(barid);   // sal[p] + ssum[(t-1)&1] visible

        float s_lag = 1.0f, inv = 1.0f;
        if (t > tb) {
            s_lag = ssum[ch][(t - 1) & 1][0] + ssum[ch][(t - 1) & 1][1];
            inv = __frcp_rn(s_lag);
        }

        const float4* av = (const float4*)sal[ch][p];
        float a0 = 0.f, a1 = 0.f, a2 = 0.f, a3 = 0.f;
        #pragma unroll
        for (int q = 0; q < 16; q++) {
            float4 v = av[q];
            a0 = fmaf(arow[4 * q],     v.x, a0);
            a1 = fmaf(arow[4 * q + 1], v.y, a1);
            a2 = fmaf(arow[4 * q + 2], v.z, a2);
            a3 = fmaf(arow[4 * q + 3], v.w, a3);
        }
        float val = ((a0 + a1) + (a2 + a3)) * (w * inv);
        sal[ch][p ^ 1][i] = val;

        // pipelined reduce of previous round's output -> s_{t-1}
        float r = prev_val;
        #pragma unroll
        for (int o = 16; o > 0; o >>= 1)
            r += __shfl_xor_sync(0xffffffffu, r, o);
        if (lane == 0) ssum[ch][t & 1][h] = r;

        if (i == 0) {
            if (t > tb) {
                int tau = t - 2;
                bool acc = (c == 0) || (tau == t0 - 2) || (tau >= t0 && tau <= tend - 3);
                if (acc) S += __logf(s_lag);
            }
            if (t >= t0) S += ml;
        }
        prev_val = val;
        w = wn; ml = mln;
        p ^= 1;
    }

    // final norm s_{tend-1}
    BAR64(barid);
    {
        float r = prev_val;
        #pragma unroll
        for (int o = 16; o > 0; o >>= 1)
            r += __shfl_xor_sync(0xffffffffu, r, o);
        if (lane == 0) ssum[ch][tend & 1][h] = r;
    }
    BAR64(barid);
    if (i == 0) {
        float s_end = ssum[ch][tend & 1][0] + ssum[ch][tend & 1][1];
        g_S1[c] = S + __logf(s_end);
    }

    // ---- last-block final reduction (replaces final_kernel) ----
    __syncthreads();
    if (tid == 0) {
        __threadfence();
        unsigned int old = atomicAdd(&g_cnt, 1u);
        slast = (old == GRID1 - 1) ? 1 : 0;
    }
    __syncthreads();
    if (slast) {
        double s = 0.0;
        for (int k = tid; k < NCH; k += 128) s += (double)g_S1[k];
        #pragma unroll
        for (int o = 16; o > 0; o >>= 1)
            s += __shfl_xor_sync(0xffffffffu, s, o);
        if (lane == 0) sred[tid >> 5] = s;
        __syncthreads();
        if (tid == 0) {
            out[0] = (float)(sred[0] + sred[1] + sred[2] + sred[3]);
            g_cnt = 0;   // reset for next graph replay
        }
    }
}

// ============================================================
extern "C" void kernel_launch(void* const* d_in, const int* in_sizes, int n_in,
                              void* d_out, int out_size) {
    const int*   x              = (const int*)d_in[0];
    const float* lambdas        = (const float*)d_in[1];
    const float* log_transition = (const float*)d_in[2];
    const float* priors         = (const float*)d_in[3];
    float* out = (float*)d_out;

    setup_kernel<<<1, 256>>>(lambdas, log_transition);
    pass0_kernel<<<T_LEN / 8, 256>>>(x);
    pass1_vec<<<GRID1, 128>>>(x, priors, out);
}

// round 13
// speedup vs baseline: 2.6962x; 1.5020x over previous
#include <cuda_runtime.h>
#include <math.h>
#include <stdint.h>

#define T_LEN 131072
#define NS 64
#define MD 8
#define NCH 4736          // 16 chunks per warp, 296 warps (one per 32-thr CTA)
#define NWARP 296
#define NSPLIT 3199       // chunks [0,3199) have L=28, rest L=27 ; 3199*28+1537*27=131071
#define BURN 20
#define LMAX 28
#define ROUNDS (BURN + LMAX + 1)   // extra round supplies endpoint norms
#define NMLP (T_LEN / 8)           // pass0 maxlog partials

// ---- static device scratch ----
__device__ float g_w[(size_t)T_LEN * NS];    // fragment-ordered per row (see pos())
__device__ float g_mlpart[NMLP];             // per-pass0-block sum of (maxlog - lgamma)
__device__ float g_loglam[NS * MD];
__device__ float g_lamsum[NS];
__device__ float g_Alin[NS * NS];
__device__ float g_S1[NCH];
__device__ float g_lgamf[32];
__device__ unsigned int g_cnt = 0;

__device__ __forceinline__ int chunk_t0(int c) {
    return (c < NSPLIT) ? 1 + 28 * c : 1 + 28 * NSPLIT + 27 * (c - NSPLIT);
}
__device__ __forceinline__ int chunk_len(int c) { return (c < NSPLIT) ? 28 : 27; }

#define CVT_BF2(r, lo, hi) asm("cvt.rn.bf16x2.f32 %0, %1, %2;" : "=r"(r) : "f"(hi), "f"(lo))
#define MMA_BF16(d, a, b0, b1) \
    asm volatile("mma.sync.aligned.m16n8k16.row.col.f32.bf16.bf16.f32 " \
                 "{%0,%1,%2,%3}, {%4,%5,%6,%7}, {%8,%9}, {%0,%1,%2,%3};" \
                 : "+f"((d)[0]), "+f"((d)[1]), "+f"((d)[2]), "+f"((d)[3]) \
                 : "r"((a)[0]), "r"((a)[1]), "r"((a)[2]), "r"((a)[3]), "r"(b0), "r"(b1))

// fragment position of state j within a w row: thread (lp = j%8/2) gets 16
// contiguous floats [lp*16, lp*16+16) ordered as nt*2 + (j&1), nt = j/8.
__device__ __forceinline__ int wpos(int j) {
    return (((j & 7) >> 1) << 4) + ((j >> 3) << 1) + (j & 1);
}

// ============================================================
__global__ void setup_kernel(const float* __restrict__ lambdas,
                             const float* __restrict__ log_transition) {
    int tid = threadIdx.x;
    if (blockIdx.x == 0) {
        for (int idx = tid; idx < NS * MD; idx += 256)
            g_loglam[idx] = logf(lambdas[idx]);
        if (tid < NS) {
            float s = 0.f;
            #pragma unroll
            for (int m = 0; m < MD; m++) s += lambdas[tid * MD + m];
            g_lamsum[tid] = s;
        }
        if (tid < 32) g_lgamf[tid] = (float)lgamma((double)tid + 1.0);
    }
    int idx = blockIdx.x * 256 + tid;
    if (idx < NS * NS) g_Alin[idx] = expf(log_transition[idx]);
}

// ============================================================
// Pass 0: fragment-ordered weights + per-block (maxlog - lgamma) partials.
// ============================================================
__global__ void __launch_bounds__(256) pass0_kernel(const int* __restrict__ x) {
    __shared__ float sll[NS * MD];
    __shared__ float slam[NS];
    __shared__ float slg[32];
    __shared__ float sml[8];
    int tid = threadIdx.x;
    for (int idx = tid; idx < NS * MD; idx += 256) sll[idx] = g_loglam[idx];
    if (tid < NS) slam[tid] = g_lamsum[tid];
    if (tid < 32) slg[tid] = g_lgamf[tid];
    __syncthreads();

    int warp = tid >> 5, lane = tid & 31;
    int t = blockIdx.x * 8 + warp;

    int4 xa = *(const int4*)&x[(size_t)t * MD];
    int4 xb = *(const int4*)&x[(size_t)t * MD + 4];
    int xv[8] = {xa.x, xa.y, xa.z, xa.w, xb.x, xb.y, xb.z, xb.w};

    float e0 = -slam[lane], e1 = -slam[lane + 32];
    #pragma unroll
    for (int m = 0; m < 8; m++) {
        float xm = (float)xv[m];
        e0 = fmaf(xm, sll[lane * MD + m], e0);
        e1 = fmaf(xm, sll[(lane + 32) * MD + m], e1);
    }
    float mx = fmaxf(e0, e1);
    #pragma unroll
    for (int o = 16; o > 0; o >>= 1)
        mx = fmaxf(mx, __shfl_xor_sync(0xffffffffu, mx, o));
    float* wr = &g_w[(size_t)t * NS];
    wr[wpos(lane)]      = expf(e0 - mx);
    wr[wpos(lane + 32)] = expf(e1 - mx);
    if (lane == 0) {
        float lg = 0.f;
        #pragma unroll
        for (int m = 0; m < 8; m++) lg += slg[xv[m] & 31];
        sml[warp] = (t == 0) ? 0.f : (mx - lg);   // t=0 handled by chunk-0 init
    }
    __syncthreads();
    if (tid == 0) {
        float s = 0.f;
        #pragma unroll
        for (int q = 0; q < 8; q++) s += sml[q];
        g_mlpart[blockIdx.x] = s;
    }
}

// ============================================================
// Pass 1: tensor-core batched vector scan. One warp = 16 chunks as rows
// of V(16x64). Per round: D = V @ A^T (32 mma), row-sums via quad shuffles,
// lag-1 normalization, scale by w, repack D->V entirely in registers
// (m16n8 D tiles exactly into m16k16 A frags). No smem, no barriers.
// Mixed chunk lengths handled by per-row predicates + 1 extra round.
// ============================================================
__global__ void __launch_bounds__(32) pass1_tc(const int* __restrict__ x,
                                               const float* __restrict__ priors,
                                               float* __restrict__ out) {
    int lane = threadIdx.x;
    int quad = lane >> 2, lp = lane & 3;
    int cb = blockIdx.x * 16;
    int c_lo = cb + quad, c_hi = cb + quad + 8;
    int t0_lo = chunk_t0(c_lo), L_lo = chunk_len(c_lo);
    int t0_hi = chunk_t0(c_hi), L_hi = chunk_len(c_hi);
    bool acc = (lp == 0);
    bool chunk0 = (blockIdx.x == 0 && quad == 0);   // row 0 = global chunk 0

    // B fragments = A matrix (constant), 4 ktiles x 8 ntiles x 2 regs
    uint32_t bfr[4][8][2];
    #pragma unroll
    for (int kt = 0; kt < 4; kt++)
        #pragma unroll
        for (int nt = 0; nt < 8; nt++) {
            const float* ar = &g_Alin[(nt * 8 + quad) * NS + kt * 16 + lp * 2];
            CVT_BF2(bfr[kt][nt][0], ar[0], ar[1]);
            CVT_BF2(bfr[kt][nt][1], ar[8], ar[9]);
        }

    // V fragments: uniform 1.0 start (burn-in washes direction)
    uint32_t vfr[4][4];
    #pragma unroll
    for (int kt = 0; kt < 4; kt++)
        #pragma unroll
        for (int e = 0; e < 4; e++) vfr[kt][e] = 0x3F803F80u;

    float wcur[32], wnxt[32];   // [0..15] lo row weights, [16..31] hi row
    {
        int tl = min(max(t0_lo - BURN, 1), T_LEN - 1);
        int th = min(max(t0_hi - BURN, 1), T_LEN - 1);
        const float4* pl = (const float4*)&g_w[(size_t)tl * NS + lp * 16];
        const float4* ph = (const float4*)&g_w[(size_t)th * NS + lp * 16];
        #pragma unroll
        for (int r = 0; r < 4; r++) {
            float4 a = __ldg(&pl[r]);
            wcur[4 * r] = a.x; wcur[4 * r + 1] = a.y; wcur[4 * r + 2] = a.z; wcur[4 * r + 3] = a.w;
            float4 b = __ldg(&ph[r]);
            wcur[16 + 4 * r] = b.x; wcur[17 + 4 * r] = b.y; wcur[18 + 4 * r] = b.z; wcur[19 + 4 * r] = b.w;
        }
    }

    float s_prev_lo = 1.f, s_prev_hi = 1.f;
    float S_lo = 0.f, S_hi = 0.f;

    for (int q = 0; q < ROUNDS; q++) {
        // prefetch next round's weights (full round to land)
        if (q + 1 < ROUNDS) {
            int tl = min(max(t0_lo - BURN + q + 1, 1), T_LEN - 1);
            int th = min(max(t0_hi - BURN + q + 1, 1), T_LEN - 1);
            const float4* pl = (const float4*)&g_w[(size_t)tl * NS + lp * 16];
            const float4* ph = (const float4*)&g_w[(size_t)th * NS + lp * 16];
            #pragma unroll
            for (int r = 0; r < 4; r++) {
                float4 a = __ldg(&pl[r]);
                wnxt[4 * r] = a.x; wnxt[4 * r + 1] = a.y; wnxt[4 * r + 2] = a.z; wnxt[4 * r + 3] = a.w;
                float4 b = __ldg(&ph[r]);
                wnxt[16 + 4 * r] = b.x; wnxt[17 + 4 * r] = b.y; wnxt[18 + 4 * r] = b.z; wnxt[19 + 4 * r] = b.w;
            }
        }

        // chunk 0 exact init, replacing its burn vector right before t0's step
        if (q == BURN && blockIdx.x == 0) {
            float ev[16];
            #pragma unroll
            for (int kt = 0; kt < 4; kt++)
                #pragma unroll
                for (int u = 0; u < 4; u++) {
                    int j = kt * 16 + lp * 2 + ((u >> 1) << 3) + (u & 1);
                    float e = priors[j] - g_lamsum[j];
                    #pragma unroll
                    for (int m = 0; m < MD; m++)
                        e = fmaf((float)x[m], g_loglam[j * MD + m], e);
                    ev[kt * 4 + u] = e;
                }
            float mx = ev[0];
            #pragma unroll
            for (int u = 1; u < 16; u++) mx = fmaxf(mx, ev[u]);
            mx = fmaxf(mx, __shfl_xor_sync(0xffffffffu, mx, 1));
            mx = fmaxf(mx, __shfl_xor_sync(0xffffffffu, mx, 2));
            if (quad == 0) {
                #pragma unroll
                for (int kt = 0; kt < 4; kt++) {
                    CVT_BF2(vfr[kt][0], __expf(ev[kt * 4 + 0] - mx), __expf(ev[kt * 4 + 1] - mx));
                    CVT_BF2(vfr[kt][2], __expf(ev[kt * 4 + 2] - mx), __expf(ev[kt * 4 + 3] - mx));
                }
                if (lane == 0) {
                    float lg0 = 0.f;
                    #pragma unroll
                    for (int m = 0; m < 8; m++) lg0 += g_lgamf[x[m] & 31];
                    S_lo = mx - lg0;
                }
            }
        }

        // D = V @ A^T  (32 mma, 8 independent n-tiles)
        float d[8][4];
        #pragma unroll
        for (int nt = 0; nt < 8; nt++)
            #pragma unroll
            for (int e = 0; e < 4; e++) d[nt][e] = 0.f;
        #pragma unroll
        for (int kt = 0; kt < 4; kt++)
            #pragma unroll
            for (int nt = 0; nt < 8; nt++)
                MMA_BF16(d[nt], vfr[kt], bfr[kt][nt][0], bfr[kt][nt][1]);

        // row-sums: s = ||v_{q-1}||_1  (A column-stochastic)
        float rl = 0.f, rh = 0.f;
        #pragma unroll
        for (int nt = 0; nt < 8; nt++) { rl += d[nt][0] + d[nt][1]; rh += d[nt][2] + d[nt][3]; }
        rl += __shfl_xor_sync(0xffffffffu, rl, 1);
        rl += __shfl_xor_sync(0xffffffffu, rl, 2);
        rh += __shfl_xor_sync(0xffffffffu, rh, 1);
        rh += __shfl_xor_sync(0xffffffffu, rh, 2);

        // accounting (telescoped; chunk 0 skips the -log s_BURN, absorbed in init)
        if (acc && q >= BURN) {
            if (q < BURN + L_lo) S_lo += __logf(s_prev_lo);
            if (q == BURN && !chunk0) S_lo -= __logf(rl);
            if (q == BURN + L_lo) S_lo += __logf(rl);
            if (q < BURN + L_hi) S_hi += __logf(s_prev_hi);
            if (q == BURN) S_hi -= __logf(rh);
            if (q == BURN + L_hi) S_hi += __logf(rh);
        }

        // scale by w * (1/s_lag), repack D -> V frags (pure in-thread)
        float il = __frcp_rn(s_prev_lo), ih = __frcp_rn(s_prev_hi);
        #pragma unroll
        for (int kt = 0; kt < 4; kt++) {
            int n0 = 2 * kt, n1 = 2 * kt + 1;
            CVT_BF2(vfr[kt][0], d[n0][0] * wcur[2 * n0] * il,      d[n0][1] * wcur[2 * n0 + 1] * il);
            CVT_BF2(vfr[kt][1], d[n0][2] * wcur[16 + 2 * n0] * ih, d[n0][3] * wcur[16 + 2 * n0 + 1] * ih);
            CVT_BF2(vfr[kt][2], d[n1][0] * wcur[2 * n1] * il,      d[n1][1] * wcur[2 * n1 + 1] * il);
            CVT_BF2(vfr[kt][3], d[n1][2] * wcur[16 + 2 * n1] * ih, d[n1][3] * wcur[16 + 2 * n1 + 1] * ih);
        }
        s_prev_lo = rl; s_prev_hi = rh;
        #pragma unroll
        for (int z = 0; z < 32; z++) wcur[z] = wnxt[z];
    }

    if (acc) { g_S1[c_lo] = S_lo; g_S1[c_hi] = S_hi; }

    // ---- last-warp final reduction ----
    __threadfence();
    unsigned int old = 0;
    if (lane == 0) old = atomicAdd(&g_cnt, 1u);
    old = __shfl_sync(0xffffffffu, old, 0);
    if (old == NWARP - 1) {
        double tot = 0.0;
        for (int k = lane; k < NCH; k += 32) tot += (double)g_S1[k];
        for (int k = lane; k < NMLP; k += 32) tot += (double)g_mlpart[k];
        #pragma unroll
        for (int o = 16; o > 0; o >>= 1)
            tot += __shfl_xor_sync(0xffffffffu, tot, o);
        if (lane == 0) { out[0] = (float)tot; g_cnt = 0; }
    }
}

// ============================================================
extern "C" void kernel_launch(void* const* d_in, const int* in_sizes, int n_in,
                              void* d_out, int out_size) {
    const int*   x              = (const int*)d_in[0];
    const float* lambdas        = (const float*)d_in[1];
    const float* log_transition = (const float*)d_in[2];
    const float* priors         = (const float*)d_in[3];
    float* out = (float*)d_out;

    setup_kernel<<<17, 256>>>(lambdas, log_transition);
    pass0_kernel<<<T_LEN / 8, 256>>>(x);
    pass1_tc<<<NWARP, 32>>>(x, priors, out);
}

// round 15
// speedup vs baseline: 3.0604x; 1.1351x over previous
#include <cuda_runtime.h>
#include <math.h>
#include <stdint.h>

#define T_LEN 131072
#define NS 64
#define MD 8
#define NCH 9472          // 16 chunks per warp, 592 warps (4 CTAs/SM, one wave)
#define NWARP 592
#define NSPLIT 7935       // chunks [0,7935) have L=14, rest L=13 ; 7935*14+1537*13=131071
#define BURN 16
#define LMAX 14
#define ROUNDS (BURN + LMAX + 1)
#define NMLP (T_LEN / 8)

// ---- static device scratch ----
__device__ float g_w[(size_t)T_LEN * NS];    // fragment-ordered per row (see wpos())
__device__ float g_mlpart[NMLP];             // per-pass0-block sum of (maxlog - lgamma)
__device__ float g_S1[NCH];
__device__ unsigned int g_cnt = 0;

__device__ __forceinline__ int chunk_t0(int c) {
    return (c < NSPLIT) ? 1 + 14 * c : 1 + 14 * NSPLIT + 13 * (c - NSPLIT);
}
__device__ __forceinline__ int chunk_len(int c) { return (c < NSPLIT) ? 14 : 13; }

#define CVT_BF2(r, lo, hi) asm("cvt.rn.bf16x2.f32 %0, %1, %2;" : "=r"(r) : "f"(hi), "f"(lo))
#define MMA_BF16(d, a, b0, b1) \
    asm volatile("mma.sync.aligned.m16n8k16.row.col.f32.bf16.bf16.f32 " \
                 "{%0,%1,%2,%3}, {%4,%5,%6,%7}, {%8,%9}, {%0,%1,%2,%3};" \
                 : "+f"((d)[0]), "+f"((d)[1]), "+f"((d)[2]), "+f"((d)[3]) \
                 : "r"((a)[0]), "r"((a)[1]), "r"((a)[2]), "r"((a)[3]), "r"(b0), "r"(b1))

// fragment position of state j within a w row
__device__ __forceinline__ int wpos(int j) {
    return (((j & 7) >> 1) << 4) + ((j >> 3) << 1) + (j & 1);
}

// ============================================================
// Pass 0 (self-contained): fragment-ordered weights + per-block
// (maxlog - lgamma) partials. loglam/lamsum/lgam computed per block.
// ============================================================
__global__ void __launch_bounds__(256) pass0_kernel(const int* __restrict__ x,
                                                    const float* __restrict__ lambdas) {
    __shared__ float sll[NS * MD];
    __shared__ float slam[NS];
    __shared__ float slg[32];
    __shared__ float sml[8];
    int tid = threadIdx.x;
    for (int idx = tid; idx < NS * MD; idx += 256) sll[idx] = __logf(lambdas[idx]);
    if (tid < NS) {
        float s = 0.f;
        #pragma unroll
        for (int m = 0; m < MD; m++) s += lambdas[tid * MD + m];
        slam[tid] = s;
    }
    if (tid < 32) slg[tid] = lgammaf((float)tid + 1.0f);
    __syncthreads();

    int warp = tid >> 5, lane = tid & 31;
    int t = blockIdx.x * 8 + warp;

    int4 xa = *(const int4*)&x[(size_t)t * MD];
    int4 xb = *(const int4*)&x[(size_t)t * MD + 4];
    int xv[8] = {xa.x, xa.y, xa.z, xa.w, xb.x, xb.y, xb.z, xb.w};

    float e0 = -slam[lane], e1 = -slam[lane + 32];
    #pragma unroll
    for (int m = 0; m < 8; m++) {
        float xm = (float)xv[m];
        e0 = fmaf(xm, sll[lane * MD + m], e0);
        e1 = fmaf(xm, sll[(lane + 32) * MD + m], e1);
    }
    float mx = fmaxf(e0, e1);
    #pragma unroll
    for (int o = 16; o > 0; o >>= 1)
        mx = fmaxf(mx, __shfl_xor_sync(0xffffffffu, mx, o));
    float* wr = &g_w[(size_t)t * NS];
    wr[wpos(lane)]      = expf(e0 - mx);
    wr[wpos(lane + 32)] = expf(e1 - mx);
    if (lane == 0) {
        float lg = 0.f;
        #pragma unroll
        for (int m = 0; m < 8; m++) lg += slg[xv[m] & 31];
        sml[warp] = (t == 0) ? 0.f : (mx - lg);   // t=0 handled by chunk-0 init
    }
    __syncthreads();
    if (tid == 0) {
        float s = 0.f;
        #pragma unroll
        for (int q = 0; q < 8; q++) s += sml[q];
        g_mlpart[blockIdx.x] = s;
    }
}

// ============================================================
// Pass 1: tensor-core batched vector scan (16 chunks per warp, rows of
// V(16x64)). D = V @ A^T per round, register-only repack, lag-1 norms,
// telescoped accounting. A-fragments built from log_transition (expf).
// Last-arriving warp reduces S1 + mlpart -> out (8-way float ILP).
// ============================================================
__global__ void __launch_bounds__(32) pass1_tc(const int* __restrict__ x,
                                               const float* __restrict__ priors,
                                               const float* __restrict__ lambdas,
                                               const float* __restrict__ log_transition,
                                               float* __restrict__ out) {
    int lane = threadIdx.x;
    int quad = lane >> 2, lp = lane & 3;
    int cb = blockIdx.x * 16;
    int c_lo = cb + quad, c_hi = cb + quad + 8;
    int t0_lo = chunk_t0(c_lo), L_lo = chunk_len(c_lo);
    int t0_hi = chunk_t0(c_hi), L_hi = chunk_len(c_hi);
    bool acc = (lp == 0);
    bool chunk0 = (blockIdx.x == 0 && quad == 0);

    // B fragments = exp(log A), built directly (one-time MUFU)
    uint32_t bfr[4][8][2];
    #pragma unroll
    for (int kt = 0; kt < 4; kt++)
        #pragma unroll
        for (int nt = 0; nt < 8; nt++) {
            const float* ar = &log_transition[(nt * 8 + quad) * NS + kt * 16 + lp * 2];
            CVT_BF2(bfr[kt][nt][0], __expf(ar[0]), __expf(ar[1]));
            CVT_BF2(bfr[kt][nt][1], __expf(ar[8]), __expf(ar[9]));
        }

    uint32_t vfr[4][4];
    #pragma unroll
    for (int kt = 0; kt < 4; kt++)
        #pragma unroll
        for (int e = 0; e < 4; e++) vfr[kt][e] = 0x3F803F80u;

    float wcur[32], wnxt[32];
    {
        int tl = min(max(t0_lo - BURN, 1), T_LEN - 1);
        int th = min(max(t0_hi - BURN, 1), T_LEN - 1);
        const float4* pl = (const float4*)&g_w[(size_t)tl * NS + lp * 16];
        const float4* ph = (const float4*)&g_w[(size_t)th * NS + lp * 16];
        #pragma unroll
        for (int r = 0; r < 4; r++) {
            float4 a = __ldg(&pl[r]);
            wcur[4 * r] = a.x; wcur[4 * r + 1] = a.y; wcur[4 * r + 2] = a.z; wcur[4 * r + 3] = a.w;
            float4 b = __ldg(&ph[r]);
            wcur[16 + 4 * r] = b.x; wcur[17 + 4 * r] = b.y; wcur[18 + 4 * r] = b.z; wcur[19 + 4 * r] = b.w;
        }
    }

    float s_prev_lo = 1.f, s_prev_hi = 1.f;
    float S_lo = 0.f, S_hi = 0.f;

    for (int q = 0; q < ROUNDS; q++) {
        if (q + 1 < ROUNDS) {
            int tl = min(max(t0_lo - BURN + q + 1, 1), T_LEN - 1);
            int th = min(max(t0_hi - BURN + q + 1, 1), T_LEN - 1);
            const float4* pl = (const float4*)&g_w[(size_t)tl * NS + lp * 16];
            const float4* ph = (const float4*)&g_w[(size_t)th * NS + lp * 16];
            #pragma unroll
            for (int r = 0; r < 4; r++) {
                float4 a = __ldg(&pl[r]);
                wnxt[4 * r] = a.x; wnxt[4 * r + 1] = a.y; wnxt[4 * r + 2] = a.z; wnxt[4 * r + 3] = a.w;
                float4 b = __ldg(&ph[r]);
                wnxt[16 + 4 * r] = b.x; wnxt[17 + 4 * r] = b.y; wnxt[18 + 4 * r] = b.z; wnxt[19 + 4 * r] = b.w;
            }
        }

        // chunk 0 exact init (replaces its burn vector just before t0's step)
        if (q == BURN && blockIdx.x == 0) {
            float ev[16];
            #pragma unroll
            for (int kt = 0; kt < 4; kt++)
                #pragma unroll
                for (int u = 0; u < 4; u++) {
                    int j = kt * 16 + lp * 2 + ((u >> 1) << 3) + (u & 1);
                    float lam = 0.f, e = priors[j];
                    #pragma unroll
                    for (int m = 0; m < MD; m++) {
                        float l = lambdas[j * MD + m];
                        lam += l;
                        e = fmaf((float)x[m], __logf(l), e);
                    }
                    ev[kt * 4 + u] = e - lam;
                }
            float mx = ev[0];
            #pragma unroll
            for (int u = 1; u < 16; u++) mx = fmaxf(mx, ev[u]);
            mx = fmaxf(mx, __shfl_xor_sync(0xffffffffu, mx, 1));
            mx = fmaxf(mx, __shfl_xor_sync(0xffffffffu, mx, 2));
            if (quad == 0) {
                #pragma unroll
                for (int kt = 0; kt < 4; kt++) {
                    CVT_BF2(vfr[kt][0], __expf(ev[kt * 4 + 0] - mx), __expf(ev[kt * 4 + 1] - mx));
                    CVT_BF2(vfr[kt][2], __expf(ev[kt * 4 + 2] - mx), __expf(ev[kt * 4 + 3] - mx));
                }
                if (lane == 0) {
                    float lg0 = 0.f;
                    #pragma unroll
                    for (int m = 0; m < 8; m++) lg0 += lgammaf((float)x[m] + 1.0f);
                    S_lo = mx - lg0;
                }
            }
        }

        // D = V @ A^T
        float d[8][4];
        #pragma unroll
        for (int nt = 0; nt < 8; nt++)
            #pragma unroll
            for (int e = 0; e < 4; e++) d[nt][e] = 0.f;
        #pragma unroll
        for (int kt = 0; kt < 4; kt++)
            #pragma unroll
            for (int nt = 0; nt < 8; nt++)
                MMA_BF16(d[nt], vfr[kt], bfr[kt][nt][0], bfr[kt][nt][1]);

        // row-sums: ||v_{q-1}||_1 (A column-stochastic)
        float rl = 0.f, rh = 0.f;
        #pragma unroll
        for (int nt = 0; nt < 8; nt++) { rl += d[nt][0] + d[nt][1]; rh += d[nt][2] + d[nt][3]; }
        rl += __shfl_xor_sync(0xffffffffu, rl, 1);
        rl += __shfl_xor_sync(0xffffffffu, rl, 2);
        rh += __shfl_xor_sync(0xffffffffu, rh, 1);
        rh += __shfl_xor_sync(0xffffffffu, rh, 2);

        if (acc && q >= BURN) {
            if (q < BURN + L_lo) S_lo += __logf(s_prev_lo);
            if (q == BURN && !chunk0) S_lo -= __logf(rl);
            if (q == BURN + L_lo) S_lo += __logf(rl);
            if (q < BURN + L_hi) S_hi += __logf(s_prev_hi);
            if (q == BURN) S_hi -= __logf(rh);
            if (q == BURN + L_hi) S_hi += __logf(rh);
        }

        float il = __frcp_rn(s_prev_lo), ih = __frcp_rn(s_prev_hi);
        #pragma unroll
        for (int kt = 0; kt < 4; kt++) {
            int n0 = 2 * kt, n1 = 2 * kt + 1;
            CVT_BF2(vfr[kt][0], d[n0][0] * wcur[2 * n0] * il,      d[n0][1] * wcur[2 * n0 + 1] * il);
            CVT_BF2(vfr[kt][1], d[n0][2] * wcur[16 + 2 * n0] * ih, d[n0][3] * wcur[16 + 2 * n0 + 1] * ih);
            CVT_BF2(vfr[kt][2], d[n1][0] * wcur[2 * n1] * il,      d[n1][1] * wcur[2 * n1 + 1] * il);
            CVT_BF2(vfr[kt][3], d[n1][2] * wcur[16 + 2 * n1] * ih, d[n1][3] * wcur[16 + 2 * n1 + 1] * ih);
        }
        s_prev_lo = rl; s_prev_hi = rh;
        #pragma unroll
        for (int z = 0; z < 32; z++) wcur[z] = wnxt[z];
    }

    if (acc) { g_S1[c_lo] = S_lo; g_S1[c_hi] = S_hi; }

    // ---- last-warp final reduction (8-way float ILP, double combine) ----
    __threadfence();
    unsigned int old = 0;
    if (lane == 0) old = atomicAdd(&g_cnt, 1u);
    old = __shfl_sync(0xffffffffu, old, 0);
    if (old == NWARP - 1) {
        float a0 = 0.f, a1 = 0.f, a2 = 0.f, a3 = 0.f;
        float a4 = 0.f, a5 = 0.f, a6 = 0.f, a7 = 0.f;
        // NCH = 9472 = 37 * 256 ; NMLP = 16384 = 64 * 256
        for (int k = lane * 8; k < NCH; k += 256) {
            float4 u = *(const float4*)&g_S1[k];
            float4 v = *(const float4*)&g_S1[k + 4];
            a0 += u.x; a1 += u.y; a2 += u.z; a3 += u.w;
            a4 += v.x; a5 += v.y; a6 += v.z; a7 += v.w;
        }
        for (int k = lane * 8; k < NMLP; k += 256) {
            float4 u = *(const float4*)&g_mlpart[k];
            float4 v = *(const float4*)&g_mlpart[k + 4];
            a0 += u.x; a1 += u.y; a2 += u.z; a3 += u.w;
            a4 += v.x; a5 += v.y; a6 += v.z; a7 += v.w;
        }
        double tot = ((double)a0 + a1) + ((double)a2 + a3)
                   + ((double)a4 + a5) + ((double)a6 + a7);
        #pragma unroll
        for (int o = 16; o > 0; o >>= 1)
            tot += __shfl_xor_sync(0xffffffffu, tot, o);
        if (lane == 0) { out[0] = (float)tot; g_cnt = 0; }
    }
}

// ============================================================
extern "C" void kernel_launch(void* const* d_in, const int* in_sizes, int n_in,
                              void* d_out, int out_size) {
    const int*   x              = (const int*)d_in[0];
    const float* lambdas        = (const float*)d_in[1];
    const float* log_transition = (const float*)d_in[2];
    const float* priors         = (const float*)d_in[3];
    float* out = (float*)d_out;

    pass0_kernel<<<T_LEN / 8, 256>>>(x, lambdas);
    pass1_tc<<<NWARP, 32>>>(x, priors, lambdas, log_transition, out);
}